// round 1
// baseline (speedup 1.0000x reference)
#include <cuda_runtime.h>
#include <math.h>

#define D_MODEL 1024
#define N_HEADS 16
#define D_HEAD  64
#define DECAY   0.99f
#define MAXROWS 4096

// ---------------- scratch (no allocations allowed) ----------------
__device__ float g_Q [MAXROWS * D_MODEL];
__device__ float g_K [MAXROWS * D_MODEL];
__device__ float g_V [MAXROWS * D_MODEL];
__device__ float g_Gp[MAXROWS * D_MODEL];
__device__ float g_R [MAXROWS * D_MODEL];
__device__ float g_NG[MAXROWS * D_MODEL];

// ---------------- tiled SGEMM with fused bias: C = A*B + bias ----------------
// A: [M,K] row-major, B: [K,N] row-major, C: [M,N]. M,N,K multiples of 64/16.
__global__ __launch_bounds__(256) void sgemm_bias(
    const float* __restrict__ A, const float* __restrict__ B,
    const float* __restrict__ bias, float* __restrict__ C,
    int M, int N, int K)
{
    __shared__ float As[64][17];   // [BM][BK+1] pad -> broadcast-friendly reads
    __shared__ float Bs[16][64];

    const int tid = threadIdx.x;
    const int tx = tid & 15, ty = tid >> 4;
    const int row0 = blockIdx.y * 64, col0 = blockIdx.x * 64;

    float acc[4][4] = {};

    for (int k0 = 0; k0 < K; k0 += 16) {
        #pragma unroll
        for (int i = tid; i < 64 * 16; i += 256) {
            int r = i >> 4, c = i & 15;
            As[r][c] = A[(size_t)(row0 + r) * K + (k0 + c)];
        }
        #pragma unroll
        for (int i = tid; i < 16 * 64; i += 256) {
            int r = i >> 6, c = i & 63;
            Bs[r][c] = B[(size_t)(k0 + r) * N + (col0 + c)];
        }
        __syncthreads();

        #pragma unroll
        for (int kk = 0; kk < 16; ++kk) {
            float a[4], bv[4];
            #pragma unroll
            for (int m = 0; m < 4; ++m) a[m] = As[ty * 4 + m][kk];
            #pragma unroll
            for (int n = 0; n < 4; ++n) bv[n] = Bs[kk][tx * 4 + n];
            #pragma unroll
            for (int m = 0; m < 4; ++m)
                #pragma unroll
                for (int n = 0; n < 4; ++n)
                    acc[m][n] = fmaf(a[m], bv[n], acc[m][n]);
        }
        __syncthreads();
    }

    #pragma unroll
    for (int m = 0; m < 4; ++m) {
        int r = row0 + ty * 4 + m;
        #pragma unroll
        for (int n = 0; n < 4; ++n) {
            int c = col0 + tx * 4 + n;
            C[(size_t)r * N + c] = acc[m][n] + bias[c];
        }
    }
}

// ---------------- retention attention ----------------
// retained[b, i, h*64+e] = sum_{j<=i} (q_i . k_j)/8 * DECAY^(i-j) * v_j[e]
// One block per (query-tile, head, batch). Streams key tiles; scores stay on-chip.
__global__ __launch_bounds__(256) void attn_kernel(
    const float* __restrict__ Q, const float* __restrict__ K,
    const float* __restrict__ V, float* __restrict__ R, int S)
{
    extern __shared__ float sm[];
    float* Qs = sm;                  // 64 x 65
    float* Ks = sm + 64 * 65;        // 64 x 65 (reused as scores tile)
    float* Vs = sm + 2 * 64 * 65;    // 64 x 64
    __shared__ float pi[64], pinv[64];

    const int tid = threadIdx.x;
    const int tx = tid & 15, ty = tid >> 4;
    const int qt = blockIdx.x, h = blockIdx.y, b = blockIdx.z;
    const int i0 = qt * 64;
    const size_t headoff = (size_t)h * D_HEAD;
    const size_t rowbase = (size_t)b * S;

    // load Q tile (row-major, coalesced)
    for (int idx = tid; idx < 4096; idx += 256) {
        int q = idx >> 6, d = idx & 63;
        Qs[q * 65 + d] = Q[(rowbase + i0 + q) * D_MODEL + headoff + d];
    }
    if (tid < 64)       pi[tid]        = powf(DECAY, (float)tid);
    else if (tid < 128) pinv[tid - 64] = powf(DECAY, -(float)(tid - 64));

    float accO[4][4] = {};

    for (int jt = 0; jt <= qt; ++jt) {
        const int j0 = jt * 64;
        __syncthreads();   // previous GEMM2 done reading Ks(=scores)/Vs; also covers Q/pi init
        for (int idx = tid; idx < 4096; idx += 256) {
            int k = idx >> 6, d = idx & 63;
            size_t g = (rowbase + j0 + k) * D_MODEL + headoff + d;
            Ks[k * 65 + d] = K[g];
            Vs[k * 64 + d] = V[g];
        }
        __syncthreads();

        // GEMM1: scores(q,k) = sum_d Q[q][d]*K[k][d]
        float accS[4][4] = {};
        #pragma unroll 8
        for (int d = 0; d < 64; ++d) {
            float qr[4], kr[4];
            #pragma unroll
            for (int m = 0; m < 4; ++m) qr[m] = Qs[(ty * 4 + m) * 65 + d];
            #pragma unroll
            for (int n = 0; n < 4; ++n) kr[n] = Ks[(tx * 4 + n) * 65 + d];
            #pragma unroll
            for (int m = 0; m < 4; ++m)
                #pragma unroll
                for (int n = 0; n < 4; ++n)
                    accS[m][n] = fmaf(qr[m], kr[n], accS[m][n]);
        }
        __syncthreads();   // done reading Ks before overwrite with scores

        // apply 1/sqrt(DH) and decay, write score tile into Ks buffer
        const float base = powf(DECAY, (float)(i0 - j0)) * 0.125f;
        const bool diag = (jt == qt);
        #pragma unroll
        for (int m = 0; m < 4; ++m) {
            int di = ty * 4 + m;
            #pragma unroll
            for (int n = 0; n < 4; ++n) {
                int dj = tx * 4 + n;
                float w = base * pi[di] * pinv[dj];
                if (diag && dj > di) w = 0.f;
                Ks[di * 65 + dj] = accS[m][n] * w;
            }
        }
        __syncthreads();

        // GEMM2: O(q,e) += sum_k scores[q][k] * V[k][e]
        #pragma unroll 8
        for (int k = 0; k < 64; ++k) {
            float sr[4], vr[4];
            #pragma unroll
            for (int m = 0; m < 4; ++m) sr[m] = Ks[(ty * 4 + m) * 65 + k];
            #pragma unroll
            for (int n = 0; n < 4; ++n) vr[n] = Vs[k * 64 + tx * 4 + n];
            #pragma unroll
            for (int m = 0; m < 4; ++m)
                #pragma unroll
                for (int n = 0; n < 4; ++n)
                    accO[m][n] = fmaf(sr[m], vr[n], accO[m][n]);
        }
    }

    #pragma unroll
    for (int m = 0; m < 4; ++m)
        #pragma unroll
        for (int n = 0; n < 4; ++n)
            R[(rowbase + i0 + ty * 4 + m) * D_MODEL + headoff + tx * 4 + n] = accO[m][n];
}

// ---------------- LayerNorm (biased var) + sigmoid gate ----------------
__global__ __launch_bounds__(256) void ln_gate_kernel(
    const float* __restrict__ Rt, const float* __restrict__ Gp,
    const float* __restrict__ gamma, const float* __restrict__ beta,
    float* __restrict__ out)
{
    const int row = blockIdx.x;
    const int tid = threadIdx.x;
    const float* r = Rt + (size_t)row * D_MODEL;

    float s = 0.f, s2 = 0.f;
    #pragma unroll
    for (int c = tid; c < D_MODEL; c += 256) { float v = r[c]; s += v; s2 = fmaf(v, v, s2); }

    __shared__ float red[64];
    #pragma unroll
    for (int off = 16; off; off >>= 1) {
        s  += __shfl_down_sync(0xffffffffu, s,  off);
        s2 += __shfl_down_sync(0xffffffffu, s2, off);
    }
    const int lane = tid & 31, w = tid >> 5;
    if (lane == 0) { red[w] = s; red[32 + w] = s2; }
    __syncthreads();
    if (tid == 0) {
        float S = 0.f, S2 = 0.f;
        #pragma unroll
        for (int i = 0; i < 8; ++i) { S += red[i]; S2 += red[32 + i]; }
        float mu  = S  * (1.f / D_MODEL);
        float var = S2 * (1.f / D_MODEL) - mu * mu;
        red[0] = mu;
        red[1] = rsqrtf(var + 1e-5f);
    }
    __syncthreads();
    const float mu = red[0], inv = red[1];

    const float* gp = Gp + (size_t)row * D_MODEL;
    float* o = out + (size_t)row * D_MODEL;
    #pragma unroll
    for (int c = tid; c < D_MODEL; c += 256) {
        float v = (r[c] - mu) * inv * gamma[c] + beta[c];
        float g = 1.f / (1.f + expf(-gp[c]));
        o[c] = v * g;
    }
}

// ---------------- launch ----------------
extern "C" void kernel_launch(void* const* d_in, const int* in_sizes, int n_in,
                              void* d_out, int out_size)
{
    const float* x     = (const float*)d_in[0];
    const float* Wq    = (const float*)d_in[1];
    const float* bq    = (const float*)d_in[2];
    const float* Wk    = (const float*)d_in[3];
    const float* bk    = (const float*)d_in[4];
    const float* Wv    = (const float*)d_in[5];
    const float* bv    = (const float*)d_in[6];
    const float* Wg    = (const float*)d_in[7];
    const float* bg    = (const float*)d_in[8];
    const float* Wo    = (const float*)d_in[9];
    const float* bo    = (const float*)d_in[10];
    const float* gamma = (const float*)d_in[11];
    const float* beta  = (const float*)d_in[12];
    float* out = (float*)d_out;

    const int M = in_sizes[0] / D_MODEL;   // B*S (= 4096)
    const int B = 2;
    const int S = M / B;

    float *Qd, *Kd, *Vd, *Gpd, *Rd, *NGd;
    cudaGetSymbolAddress((void**)&Qd,  g_Q);
    cudaGetSymbolAddress((void**)&Kd,  g_K);
    cudaGetSymbolAddress((void**)&Vd,  g_V);
    cudaGetSymbolAddress((void**)&Gpd, g_Gp);
    cudaGetSymbolAddress((void**)&Rd,  g_R);
    cudaGetSymbolAddress((void**)&NGd, g_NG);

    dim3 ggrid(D_MODEL / 64, M / 64);   // (16, 64)
    sgemm_bias<<<ggrid, 256>>>(x, Wq, bq, Qd,  M, D_MODEL, D_MODEL);
    sgemm_bias<<<ggrid, 256>>>(x, Wk, bk, Kd,  M, D_MODEL, D_MODEL);
    sgemm_bias<<<ggrid, 256>>>(x, Wv, bv, Vd,  M, D_MODEL, D_MODEL);
    sgemm_bias<<<ggrid, 256>>>(x, Wg, bg, Gpd, M, D_MODEL, D_MODEL);

    const int ATT_SMEM = (64 * 65 * 2 + 64 * 64) * (int)sizeof(float);  // 49664 B
    cudaFuncSetAttribute(attn_kernel, cudaFuncAttributeMaxDynamicSharedMemorySize, ATT_SMEM);
    attn_kernel<<<dim3(S / 64, N_HEADS, B), 256, ATT_SMEM>>>(Qd, Kd, Vd, Rd, S);

    ln_gate_kernel<<<M, 256>>>(Rd, Gpd, gamma, beta, NGd);

    sgemm_bias<<<ggrid, 256>>>(NGd, Wo, bo, out, M, D_MODEL, D_MODEL);
}

// round 2
// speedup vs baseline: 1.3988x; 1.3988x over previous
#include <cuda_runtime.h>
#include <math.h>

#define D_MODEL 1024
#define N_HEADS 16
#define D_HEAD  64
#define DECAY   0.99f
#define MAXROWS 4096

// ---------------- scratch (no allocations allowed) ----------------
__device__ float g_Q [MAXROWS * D_MODEL];
__device__ float g_K [MAXROWS * D_MODEL];
__device__ float g_V [MAXROWS * D_MODEL];
__device__ float g_Gp[MAXROWS * D_MODEL];
__device__ float g_R [MAXROWS * D_MODEL];
__device__ float g_NG[MAXROWS * D_MODEL];

// =======================================================================
// 128x128x16 SGEMM core, 8x8 microtile, vectorized smem access.
// A:[4096,1024] row-major, W:[1024,1024] row-major, C[row0..+128][col0..+128]
// =======================================================================
__device__ __forceinline__ void gemm128_core(
    const float* __restrict__ A, const float* __restrict__ W,
    const float* __restrict__ bias, float* __restrict__ C,
    int row0, int col0)
{
    __shared__ float As[16][132];   // [k][m] transposed, pad 132 -> 2-way stores, aligned reads
    __shared__ float Bs[16][128];   // [k][n] natural

    const int tid = threadIdx.x;
    const int tx = tid & 15;        // n block: 8 cols each
    const int ty = tid >> 4;        // m block: 8 rows each

    float acc[8][8] = {};

    for (int k0 = 0; k0 < 1024; k0 += 16) {
        // A tile 128x16 -> transposed store
        #pragma unroll
        for (int i = 0; i < 2; ++i) {
            int idx = tid + i * 256;
            int r  = idx >> 2;
            int c4 = (idx & 3) * 4;
            float4 v = *(const float4*)&A[(size_t)(row0 + r) * 1024 + k0 + c4];
            As[c4 + 0][r] = v.x; As[c4 + 1][r] = v.y;
            As[c4 + 2][r] = v.z; As[c4 + 3][r] = v.w;
        }
        // B tile 16x128 -> direct vectorized store
        #pragma unroll
        for (int i = 0; i < 2; ++i) {
            int idx = tid + i * 256;
            int r  = idx >> 5;
            int c4 = (idx & 31) * 4;
            *(float4*)&Bs[r][c4] =
                *(const float4*)&W[(size_t)(k0 + r) * 1024 + col0 + c4];
        }
        __syncthreads();

        #pragma unroll
        for (int kk = 0; kk < 16; ++kk) {
            float a[8], b[8];
            *(float4*)&a[0] = *(const float4*)&As[kk][ty * 8];
            *(float4*)&a[4] = *(const float4*)&As[kk][ty * 8 + 4];
            *(float4*)&b[0] = *(const float4*)&Bs[kk][tx * 8];
            *(float4*)&b[4] = *(const float4*)&Bs[kk][tx * 8 + 4];
            #pragma unroll
            for (int m = 0; m < 8; ++m)
                #pragma unroll
                for (int n = 0; n < 8; ++n)
                    acc[m][n] = fmaf(a[m], b[n], acc[m][n]);
        }
        __syncthreads();
    }

    float bv[8];
    *(float4*)&bv[0] = *(const float4*)&bias[col0 + tx * 8];
    *(float4*)&bv[4] = *(const float4*)&bias[col0 + tx * 8 + 4];

    #pragma unroll
    for (int m = 0; m < 8; ++m) {
        size_t rbase = (size_t)(row0 + ty * 8 + m) * 1024 + col0 + tx * 8;
        *(float4*)&C[rbase]     = make_float4(acc[m][0] + bv[0], acc[m][1] + bv[1],
                                              acc[m][2] + bv[2], acc[m][3] + bv[3]);
        *(float4*)&C[rbase + 4] = make_float4(acc[m][4] + bv[4], acc[m][5] + bv[5],
                                              acc[m][6] + bv[6], acc[m][7] + bv[7]);
    }
}

// 4 projections fused into one launch: blockIdx.z selects {q,k,v,g}
__global__ __launch_bounds__(256, 2) void proj4_kernel(
    const float* __restrict__ x,
    const float* __restrict__ Wq, const float* __restrict__ bq, float* __restrict__ Qo,
    const float* __restrict__ Wk, const float* __restrict__ bk, float* __restrict__ Ko,
    const float* __restrict__ Wv, const float* __restrict__ bv, float* __restrict__ Vo,
    const float* __restrict__ Wg, const float* __restrict__ bg, float* __restrict__ Go)
{
    const float* W; const float* bias; float* C;
    switch (blockIdx.z) {
        case 0:  W = Wq; bias = bq; C = Qo; break;
        case 1:  W = Wk; bias = bk; C = Ko; break;
        case 2:  W = Wv; bias = bv; C = Vo; break;
        default: W = Wg; bias = bg; C = Go; break;
    }
    gemm128_core(x, W, bias, C, blockIdx.y * 128, blockIdx.x * 128);
}

__global__ __launch_bounds__(256, 2) void sgemm_bias(
    const float* __restrict__ A, const float* __restrict__ W,
    const float* __restrict__ bias, float* __restrict__ C)
{
    gemm128_core(A, W, bias, C, blockIdx.y * 128, blockIdx.x * 128);
}

// =======================================================================
// Retention attention: 128 queries x 64 keys per iter, 8x4 microtile.
// retained[b,i,h*64+e] = sum_{j<=i} (q_i.k_j)/8 * DECAY^(i-j) * v_j[e]
// =======================================================================
__global__ __launch_bounds__(256, 1) void attn_kernel(
    const float* __restrict__ Q, const float* __restrict__ K,
    const float* __restrict__ V, float* __restrict__ R, int S)
{
    extern __shared__ float sm[];
    float* QsT = sm;                    // [64][132]  (d, q)
    float* KsT = QsT + 64 * 132;        // [64][68]   (d, k)
    float* Vs  = KsT + 64 * 68;         // [64][64]   (k, e)
    float* Ss  = Vs  + 64 * 64;         // [64][132]  (k, q)
    __shared__ float pi[128], pinv[64];

    const int tid = threadIdx.x;
    const int tx = tid & 15;            // k (x4) / e (x4)
    const int ty = tid >> 4;            // q (x8)
    const int qt = blockIdx.x, h = blockIdx.y, b = blockIdx.z;
    const int i0 = qt * 128;
    const size_t rowbase = (size_t)b * S;
    const int headoff = h * D_HEAD;

    // load Q tile (128 x 64) transposed
    #pragma unroll
    for (int i = 0; i < 8; ++i) {
        int idx = tid + i * 256;
        int q  = idx >> 4;
        int d4 = (idx & 15) * 4;
        float4 v = *(const float4*)&Q[(rowbase + i0 + q) * 1024 + headoff + d4];
        QsT[(d4 + 0) * 132 + q] = v.x; QsT[(d4 + 1) * 132 + q] = v.y;
        QsT[(d4 + 2) * 132 + q] = v.z; QsT[(d4 + 3) * 132 + q] = v.w;
    }
    if (tid < 128)      pi[tid]         = powf(DECAY, (float)tid);
    else if (tid < 192) pinv[tid - 128] = powf(DECAY, -(float)(tid - 128));

    float accO[8][4] = {};
    const int jtmax = 2 * qt + 1;

    for (int jt = 0; jt <= jtmax; ++jt) {
        const int j0 = jt * 64;
        __syncthreads();   // prev GEMM2 done with Vs/Ss; first iter: QsT/pi ready

        // load K (transposed) and V tiles, 64x64 each
        #pragma unroll
        for (int i = 0; i < 4; ++i) {
            int idx = tid + i * 256;
            int k  = idx >> 4;
            int d4 = (idx & 15) * 4;
            size_t g = (rowbase + j0 + k) * 1024 + headoff + d4;
            float4 kv = *(const float4*)&K[g];
            KsT[(d4 + 0) * 68 + k] = kv.x; KsT[(d4 + 1) * 68 + k] = kv.y;
            KsT[(d4 + 2) * 68 + k] = kv.z; KsT[(d4 + 3) * 68 + k] = kv.w;
            *(float4*)&Vs[k * 64 + d4] = *(const float4*)&V[g];
        }
        __syncthreads();

        // GEMM1: scores[q][k] = sum_d Q[q][d]*K[k][d]
        float accS[8][4] = {};
        #pragma unroll 16
        for (int d = 0; d < 64; ++d) {
            float qv[8], kv[4];
            *(float4*)&qv[0] = *(const float4*)&QsT[d * 132 + ty * 8];
            *(float4*)&qv[4] = *(const float4*)&QsT[d * 132 + ty * 8 + 4];
            *(float4*)&kv[0] = *(const float4*)&KsT[d * 68 + tx * 4];
            #pragma unroll
            for (int m = 0; m < 8; ++m)
                #pragma unroll
                for (int n = 0; n < 4; ++n)
                    accS[m][n] = fmaf(qv[m], kv[n], accS[m][n]);
        }

        // scale + decay + causal mask, store transposed Ss[k][q]
        const float base = powf(DECAY, (float)(i0 - j0)) * 0.125f;
        const bool maskt = (jt >= 2 * qt);
        const int joff = j0 - i0;
        #pragma unroll
        for (int n = 0; n < 4; ++n) {
            int dj = tx * 4 + n;
            float wj = base * pinv[dj];
            float t[8];
            #pragma unroll
            for (int m = 0; m < 8; ++m) {
                int di = ty * 8 + m;
                float w = wj * pi[di];
                if (maskt && (joff + dj > di)) w = 0.f;
                t[m] = accS[m][n] * w;
            }
            *(float4*)&Ss[dj * 132 + ty * 8]     = make_float4(t[0], t[1], t[2], t[3]);
            *(float4*)&Ss[dj * 132 + ty * 8 + 4] = make_float4(t[4], t[5], t[6], t[7]);
        }
        __syncthreads();

        // GEMM2: O[q][e] += sum_k scores[q][k] * V[k][e]
        #pragma unroll 16
        for (int k = 0; k < 64; ++k) {
            float sv[8], vv[4];
            *(float4*)&sv[0] = *(const float4*)&Ss[k * 132 + ty * 8];
            *(float4*)&sv[4] = *(const float4*)&Ss[k * 132 + ty * 8 + 4];
            *(float4*)&vv[0] = *(const float4*)&Vs[k * 64 + tx * 4];
            #pragma unroll
            for (int m = 0; m < 8; ++m)
                #pragma unroll
                for (int n = 0; n < 4; ++n)
                    accO[m][n] = fmaf(sv[m], vv[n], accO[m][n]);
        }
    }

    #pragma unroll
    for (int m = 0; m < 8; ++m) {
        *(float4*)&R[(rowbase + i0 + ty * 8 + m) * 1024 + headoff + tx * 4] =
            make_float4(accO[m][0], accO[m][1], accO[m][2], accO[m][3]);
    }
}

// ---------------- LayerNorm (biased var) + sigmoid gate ----------------
__global__ __launch_bounds__(256) void ln_gate_kernel(
    const float* __restrict__ Rt, const float* __restrict__ Gp,
    const float* __restrict__ gamma, const float* __restrict__ beta,
    float* __restrict__ out)
{
    const int row = blockIdx.x;
    const int tid = threadIdx.x;
    const float* r = Rt + (size_t)row * D_MODEL;

    float s = 0.f, s2 = 0.f;
    #pragma unroll
    for (int c = tid; c < D_MODEL; c += 256) { float v = r[c]; s += v; s2 = fmaf(v, v, s2); }

    __shared__ float red[64];
    #pragma unroll
    for (int off = 16; off; off >>= 1) {
        s  += __shfl_down_sync(0xffffffffu, s,  off);
        s2 += __shfl_down_sync(0xffffffffu, s2, off);
    }
    const int lane = tid & 31, w = tid >> 5;
    if (lane == 0) { red[w] = s; red[32 + w] = s2; }
    __syncthreads();
    if (tid == 0) {
        float S = 0.f, S2 = 0.f;
        #pragma unroll
        for (int i = 0; i < 8; ++i) { S += red[i]; S2 += red[32 + i]; }
        float mu  = S  * (1.f / D_MODEL);
        float var = S2 * (1.f / D_MODEL) - mu * mu;
        red[0] = mu;
        red[1] = rsqrtf(var + 1e-5f);
    }
    __syncthreads();
    const float mu = red[0], inv = red[1];

    const float* gp = Gp + (size_t)row * D_MODEL;
    float* o = out + (size_t)row * D_MODEL;
    #pragma unroll
    for (int c = tid; c < D_MODEL; c += 256) {
        float v = (r[c] - mu) * inv * gamma[c] + beta[c];
        float g = 1.f / (1.f + expf(-gp[c]));
        o[c] = v * g;
    }
}

// ---------------- launch ----------------
extern "C" void kernel_launch(void* const* d_in, const int* in_sizes, int n_in,
                              void* d_out, int out_size)
{
    const float* x     = (const float*)d_in[0];
    const float* Wq    = (const float*)d_in[1];
    const float* bq    = (const float*)d_in[2];
    const float* Wk    = (const float*)d_in[3];
    const float* bk    = (const float*)d_in[4];
    const float* Wv    = (const float*)d_in[5];
    const float* bv    = (const float*)d_in[6];
    const float* Wg    = (const float*)d_in[7];
    const float* bg    = (const float*)d_in[8];
    const float* Wo    = (const float*)d_in[9];
    const float* bo    = (const float*)d_in[10];
    const float* gamma = (const float*)d_in[11];
    const float* beta  = (const float*)d_in[12];
    float* out = (float*)d_out;

    const int M = in_sizes[0] / D_MODEL;   // B*S = 4096
    const int B = 2;
    const int S = M / B;                   // 2048

    float *Qd, *Kd, *Vd, *Gpd, *Rd, *NGd;
    cudaGetSymbolAddress((void**)&Qd,  g_Q);
    cudaGetSymbolAddress((void**)&Kd,  g_K);
    cudaGetSymbolAddress((void**)&Vd,  g_V);
    cudaGetSymbolAddress((void**)&Gpd, g_Gp);
    cudaGetSymbolAddress((void**)&Rd,  g_R);
    cudaGetSymbolAddress((void**)&NGd, g_NG);

    // fused 4-way projection: grid (N/128, M/128, 4)
    dim3 pg(D_MODEL / 128, M / 128, 4);
    proj4_kernel<<<pg, 256>>>(x, Wq, bq, Qd, Wk, bk, Kd, Wv, bv, Vd, Wg, bg, Gpd);

    const int ATT_SMEM = (64 * 132 + 64 * 68 + 64 * 64 + 64 * 132) * (int)sizeof(float);
    cudaFuncSetAttribute(attn_kernel, cudaFuncAttributeMaxDynamicSharedMemorySize, ATT_SMEM);
    attn_kernel<<<dim3(S / 128, N_HEADS, B), 256, ATT_SMEM>>>(Qd, Kd, Vd, Rd, S);

    ln_gate_kernel<<<M, 256>>>(Rd, Gpd, gamma, beta, NGd);

    sgemm_bias<<<dim3(D_MODEL / 128, M / 128), 256>>>(NGd, Wo, bo, out);
}